// round 1
// baseline (speedup 1.0000x reference)
#include <cuda_runtime.h>
#include <math.h>
#include <stdint.h>

#define NUM_HEADS 16
#define DMODEL    1024
#define DK        64
#define BATCH     2
#define SEQ       2048
#define MROWS     (BATCH * SEQ)      // 4096
#define KDIM      1024

// ---------------- scratch (device globals; no allocation allowed) ----------
// g_QKV[z][b][h][s][dk], z in {Q,K,V}
__device__ __align__(128) float g_QKV[3ull * BATCH * NUM_HEADS * SEQ * DK];
// attention output, merged-head layout [b*S, DMODEL]
__device__ __align__(128) float g_O[(size_t)MROWS * DMODEL];

// ==========================================================================
// GEMM: C = A @ W^T + bias.   A:[M,K] row-major, W:[N,K] row-major.
// M=4096, N=1024, K=1024. BM=BN=128, BK=8, 256 threads, 8x8 per thread.
// SPLIT: write C[m, n] to g-style [b,h,s,dk] layout instead of row-major.
// ==========================================================================
template <bool SPLIT>
__device__ __forceinline__ void gemm_body(const float* __restrict__ A,
                                          const float* __restrict__ W,
                                          const float* __restrict__ bias,
                                          float* __restrict__ C)
{
    __shared__ float As[8][132];   // padded: stride 132 keeps 16B alignment,
    __shared__ float Bs[8][132];   // spreads transpose-store banks

    const int t  = threadIdx.x;
    const int tx = t & 15;         // 0..15 -> 8 output cols each
    const int ty = t >> 4;         // 0..15 -> 8 output rows each

    const int rowBlk = blockIdx.y * 128;
    const int colBlk = blockIdx.x * 128;

    // global-load assignment: each thread loads one float4 of A and W per tile
    const int lr = t >> 1;          // 0..127
    const int lc = (t & 1) * 4;     // 0 or 4

    const float* Aptr = A + (size_t)(rowBlk + lr) * KDIM + lc;
    const float* Wptr = W + (size_t)(colBlk + lr) * KDIM + lc;

    float4 a4 = *(const float4*)Aptr;
    float4 b4 = *(const float4*)Wptr;

    float acc[8][8];
#pragma unroll
    for (int i = 0; i < 8; i++)
#pragma unroll
        for (int j = 0; j < 8; j++) acc[i][j] = 0.f;

    for (int k0 = 0; k0 < KDIM; k0 += 8) {
        // commit prefetched tile to smem (transposed: [k][row])
        As[lc + 0][lr] = a4.x;  As[lc + 1][lr] = a4.y;
        As[lc + 2][lr] = a4.z;  As[lc + 3][lr] = a4.w;
        Bs[lc + 0][lr] = b4.x;  Bs[lc + 1][lr] = b4.y;
        Bs[lc + 2][lr] = b4.z;  Bs[lc + 3][lr] = b4.w;
        __syncthreads();

        // prefetch next tile into registers (hidden under compute)
        if (k0 + 8 < KDIM) {
            a4 = *(const float4*)(Aptr + k0 + 8);
            b4 = *(const float4*)(Wptr + k0 + 8);
        }

        float ar[8], br[8];
#pragma unroll
        for (int kk = 0; kk < 8; kk++) {
            *(float4*)&ar[0] = *(const float4*)&As[kk][ty * 8 + 0];
            *(float4*)&ar[4] = *(const float4*)&As[kk][ty * 8 + 4];
            *(float4*)&br[0] = *(const float4*)&Bs[kk][tx * 8 + 0];
            *(float4*)&br[4] = *(const float4*)&Bs[kk][tx * 8 + 4];
#pragma unroll
            for (int i = 0; i < 8; i++)
#pragma unroll
                for (int j = 0; j < 8; j++)
                    acc[i][j] += ar[i] * br[j];
        }
        __syncthreads();
    }

    // epilogue: add bias, store
#pragma unroll
    for (int i = 0; i < 8; i++) {
        const int m = rowBlk + ty * 8 + i;
#pragma unroll
        for (int j = 0; j < 8; j += 4) {
            const int n = colBlk + tx * 8 + j;
            float4 v;
            v.x = acc[i][j + 0] + bias[n + 0];
            v.y = acc[i][j + 1] + bias[n + 1];
            v.z = acc[i][j + 2] + bias[n + 2];
            v.w = acc[i][j + 3] + bias[n + 3];
            if (SPLIT) {
                const int b = m >> 11;          // m / SEQ
                const int s = m & (SEQ - 1);
                const int h = n >> 6;           // n / DK
                const int d = n & (DK - 1);
                *(float4*)&C[(((size_t)(b * NUM_HEADS + h) * SEQ + s) * DK) + d] = v;
            } else {
                *(float4*)&C[(size_t)m * DMODEL + n] = v;
            }
        }
    }
}

__global__ __launch_bounds__(256, 2)
void qkv_proj_kernel(const float* __restrict__ Qin,
                     const float* __restrict__ Kin,
                     const float* __restrict__ Vin,
                     const float* __restrict__ Wq, const float* __restrict__ bq,
                     const float* __restrict__ Wk, const float* __restrict__ bk,
                     const float* __restrict__ Wv, const float* __restrict__ bv)
{
    const int z = blockIdx.z;
    const float* A    = (z == 0) ? Qin : (z == 1) ? Kin : Vin;
    const float* W    = (z == 0) ? Wq  : (z == 1) ? Wk  : Wv;
    const float* bias = (z == 0) ? bq  : (z == 1) ? bk  : bv;
    float* out = g_QKV + (size_t)z * BATCH * NUM_HEADS * SEQ * DK;
    gemm_body<true>(A, W, bias, out);
}

__global__ __launch_bounds__(256, 2)
void out_proj_kernel(const float* __restrict__ Wo,
                     const float* __restrict__ bo,
                     float* __restrict__ out)
{
    gemm_body<false>(g_O, Wo, bo, out);
}

// ==========================================================================
// Flash attention, fp32. One CTA = 64 queries of one (b,h).
// 256 threads (16x16), 4x4 register tiles over the 64x64 S tile.
// smem: Qs[d][i] (T), KP[d][j] (T, aliased with P[i][j]), Vs[j][d].
// ==========================================================================
#define FPAD 68  // row stride (floats): multiple of 4 (16B alignment for LDS.128)
#define SM_Q  0
#define SM_KP (64 * FPAD)
#define SM_V  (2 * 64 * FPAD)
#define FLASH_SMEM (3 * 64 * FPAD * 4)

__global__ __launch_bounds__(256)
void flash_attn_kernel()
{
    extern __shared__ float sm[];
    float* Qs = sm + SM_Q;
    float* KP = sm + SM_KP;
    float* Vs = sm + SM_V;

    const int t  = threadIdx.x;
    const int tx = t & 15;
    const int ty = t >> 4;
    const int q0 = blockIdx.x * 64;
    const int h  = blockIdx.y;
    const int b  = blockIdx.z;

    const size_t headBase = ((size_t)b * NUM_HEADS + h) * SEQ * DK;
    const float* Qg = g_QKV + 0ull * BATCH * NUM_HEADS * SEQ * DK + headBase;
    const float* Kg = g_QKV + 1ull * BATCH * NUM_HEADS * SEQ * DK + headBase;
    const float* Vg = g_QKV + 2ull * BATCH * NUM_HEADS * SEQ * DK + headBase;

    const float SCALE = 0.125f;  // 1/sqrt(64)

    // ---- load Q tile, transposed Qs[d][i], scale folded in ----
    {
        const int ds = ty * 4;
        const int rb = tx;
#pragma unroll
        for (int p = 0; p < 4; p++) {
            const int r = rb + p * 16;
            float4 q = *(const float4*)&Qg[(size_t)(q0 + r) * DK + ds];
            Qs[(ds + 0) * FPAD + r] = q.x * SCALE;
            Qs[(ds + 1) * FPAD + r] = q.y * SCALE;
            Qs[(ds + 2) * FPAD + r] = q.z * SCALE;
            Qs[(ds + 3) * FPAD + r] = q.w * SCALE;
        }
    }

    float o[4][4];
    float m_i[4], l_i[4];
#pragma unroll
    for (int i = 0; i < 4; i++) {
        m_i[i] = -1e30f; l_i[i] = 0.f;
#pragma unroll
        for (int d = 0; d < 4; d++) o[i][d] = 0.f;
    }
    __syncthreads();

    for (int j0 = 0; j0 < SEQ; j0 += 64) {
        // ---- load K (transposed -> KP[d][j]) and V (direct -> Vs[j][d]) ----
        {
            const int ds = ty * 4;
            const int rb = tx;
#pragma unroll
            for (int p = 0; p < 4; p++) {
                const int r = rb + p * 16;
                float4 k = *(const float4*)&Kg[(size_t)(j0 + r) * DK + ds];
                KP[(ds + 0) * FPAD + r] = k.x;
                KP[(ds + 1) * FPAD + r] = k.y;
                KP[(ds + 2) * FPAD + r] = k.z;
                KP[(ds + 3) * FPAD + r] = k.w;
            }
            const int dv = tx * 4;
            const int jb = ty;
#pragma unroll
            for (int p = 0; p < 4; p++) {
                const int j = jb + p * 16;
                float4 v = *(const float4*)&Vg[(size_t)(j0 + j) * DK + dv];
                *(float4*)&Vs[j * FPAD + dv] = v;
            }
        }
        __syncthreads();

        // ---- GEMM1: S = (Q*scale) @ K^T ----
        float s[4][4];
#pragma unroll
        for (int i = 0; i < 4; i++)
#pragma unroll
            for (int j = 0; j < 4; j++) s[i][j] = 0.f;

#pragma unroll 16
        for (int d = 0; d < 64; d++) {
            float4 a  = *(const float4*)&Qs[d * FPAD + ty * 4];
            float4 bv = *(const float4*)&KP[d * FPAD + tx * 4];
            s[0][0] += a.x * bv.x; s[0][1] += a.x * bv.y; s[0][2] += a.x * bv.z; s[0][3] += a.x * bv.w;
            s[1][0] += a.y * bv.x; s[1][1] += a.y * bv.y; s[1][2] += a.y * bv.z; s[1][3] += a.y * bv.w;
            s[2][0] += a.z * bv.x; s[2][1] += a.z * bv.y; s[2][2] += a.z * bv.z; s[2][3] += a.z * bv.w;
            s[3][0] += a.w * bv.x; s[3][1] += a.w * bv.y; s[3][2] += a.w * bv.z; s[3][3] += a.w * bv.w;
        }

        // ---- online softmax (row reductions across the 16 tx lanes) ----
#pragma unroll
        for (int i = 0; i < 4; i++) {
            float mx = fmaxf(fmaxf(s[i][0], s[i][1]), fmaxf(s[i][2], s[i][3]));
#pragma unroll
            for (int off = 1; off < 16; off <<= 1)
                mx = fmaxf(mx, __shfl_xor_sync(0xffffffffu, mx, off));
            const float mn   = fmaxf(m_i[i], mx);
            const float corr = __expf(m_i[i] - mn);
            m_i[i] = mn;
            float rs = 0.f;
#pragma unroll
            for (int j = 0; j < 4; j++) {
                s[i][j] = __expf(s[i][j] - mn);
                rs += s[i][j];
            }
#pragma unroll
            for (int off = 1; off < 16; off <<= 1)
                rs += __shfl_xor_sync(0xffffffffu, rs, off);
            l_i[i] = l_i[i] * corr + rs;
#pragma unroll
            for (int d = 0; d < 4; d++) o[i][d] *= corr;
        }

        __syncthreads();  // everyone done reading KP (K) before P overwrite

        // ---- write P row-major into KP region: P[i][j], conflict-free f4 ----
#pragma unroll
        for (int i = 0; i < 4; i++) {
            float4 pv = make_float4(s[i][0], s[i][1], s[i][2], s[i][3]);
            *(float4*)&KP[(ty * 4 + i) * FPAD + tx * 4] = pv;
        }
        __syncthreads();

        // ---- GEMM2: O += P @ V ----
#pragma unroll 16
        for (int j = 0; j < 64; j++) {
            float4 bv = *(const float4*)&Vs[j * FPAD + tx * 4];
            float a0 = KP[(ty * 4 + 0) * FPAD + j];
            float a1 = KP[(ty * 4 + 1) * FPAD + j];
            float a2 = KP[(ty * 4 + 2) * FPAD + j];
            float a3 = KP[(ty * 4 + 3) * FPAD + j];
            o[0][0] += a0 * bv.x; o[0][1] += a0 * bv.y; o[0][2] += a0 * bv.z; o[0][3] += a0 * bv.w;
            o[1][0] += a1 * bv.x; o[1][1] += a1 * bv.y; o[1][2] += a1 * bv.z; o[1][3] += a1 * bv.w;
            o[2][0] += a2 * bv.x; o[2][1] += a2 * bv.y; o[2][2] += a2 * bv.z; o[2][3] += a2 * bv.w;
            o[3][0] += a3 * bv.x; o[3][1] += a3 * bv.y; o[3][2] += a3 * bv.z; o[3][3] += a3 * bv.w;
        }
        __syncthreads();  // before next tile overwrites KP / Vs
    }

    // ---- epilogue: normalize, write merged-head layout [b*S, DMODEL] ----
#pragma unroll
    for (int i = 0; i < 4; i++) {
        const int rowg = q0 + ty * 4 + i;
        const float inv = 1.f / l_i[i];
        float4 ov = make_float4(o[i][0] * inv, o[i][1] * inv,
                                o[i][2] * inv, o[i][3] * inv);
        *(float4*)&g_O[((size_t)b * SEQ + rowg) * DMODEL + h * DK + tx * 4] = ov;
    }
}

// ==========================================================================
// launch
// ==========================================================================
extern "C" void kernel_launch(void* const* d_in, const int* in_sizes, int n_in,
                              void* d_out, int out_size)
{
    (void)in_sizes; (void)n_in; (void)out_size;
    const float* Qin = (const float*)d_in[0];
    const float* Kin = (const float*)d_in[1];
    const float* Vin = (const float*)d_in[2];
    const float* Wq  = (const float*)d_in[3];
    const float* bq  = (const float*)d_in[4];
    const float* Wk  = (const float*)d_in[5];
    const float* bk  = (const float*)d_in[6];
    const float* Wv  = (const float*)d_in[7];
    const float* bv  = (const float*)d_in[8];
    const float* Wo  = (const float*)d_in[9];
    const float* bo  = (const float*)d_in[10];
    float* out = (float*)d_out;

    // idempotent, non-allocating, capture-safe
    cudaFuncSetAttribute(flash_attn_kernel,
                         cudaFuncAttributeMaxDynamicSharedMemorySize, FLASH_SMEM);

    dim3 gProj(DMODEL / 128, MROWS / 128, 3);
    qkv_proj_kernel<<<gProj, 256>>>(Qin, Kin, Vin, Wq, bq, Wk, bk, Wv, bv);

    dim3 gAttn(SEQ / 64, NUM_HEADS, BATCH);
    flash_attn_kernel<<<gAttn, 256, FLASH_SMEM>>>();

    dim3 gOut(DMODEL / 128, MROWS / 128, 1);
    out_proj_kernel<<<gOut, 256>>>(Wo, bo, out);
}

// round 3
// speedup vs baseline: 1.2918x; 1.2918x over previous
#include <cuda_runtime.h>
#include <cuda_bf16.h>
#include <math.h>
#include <stdint.h>

#define NUM_HEADS 16
#define DMODEL    1024
#define DK        64
#define BATCH     2
#define SEQ       2048
#define MROWS     (BATCH * SEQ)      // 4096
#define KDIM      1024

// ---------------- scratch (device globals; no allocation allowed) ----------
__device__ __align__(128) float g_QKV[3ull * BATCH * NUM_HEADS * SEQ * DK];
__device__ __align__(128) float g_O[(size_t)MROWS * DMODEL];

// ==========================================================================
// warp-MMA helpers (arch-agnostic PTX: valid on plain sm_103 target)
// ==========================================================================
__device__ __forceinline__ uint32_t smem_u32(const void* p) {
    uint32_t a;
    asm("{ .reg .u64 t; cvta.to.shared.u64 t, %1; cvt.u32.u64 %0, t; }"
        : "=r"(a) : "l"(p));
    return a;
}

__device__ __forceinline__ void ldsm4(uint32_t* r, uint32_t addr) {
    asm volatile("ldmatrix.sync.aligned.m8n8.x4.shared.b16 {%0,%1,%2,%3}, [%4];"
                 : "=r"(r[0]), "=r"(r[1]), "=r"(r[2]), "=r"(r[3])
                 : "r"(addr));
}

__device__ __forceinline__ void mma16816(float* c, const uint32_t* a,
                                         uint32_t b0, uint32_t b1) {
    asm volatile(
        "mma.sync.aligned.m16n8k16.row.col.f32.bf16.bf16.f32 "
        "{%0,%1,%2,%3}, {%4,%5,%6,%7}, {%8,%9}, {%0,%1,%2,%3};"
        : "+f"(c[0]), "+f"(c[1]), "+f"(c[2]), "+f"(c[3])
        : "r"(a[0]), "r"(a[1]), "r"(a[2]), "r"(a[3]), "r"(b0), "r"(b1));
}

__device__ __forceinline__ uint32_t packbf(__nv_bfloat16 a, __nv_bfloat16 b) {
    return (uint32_t)__bfloat16_as_ushort(a) |
           ((uint32_t)__bfloat16_as_ushort(b) << 16);
}

// fp32x4 -> hi bf16x4 (8B) + lo bf16x4 (8B)
__device__ __forceinline__ void cvt_split8(float4 v, char* hiP, char* loP) {
    __nv_bfloat16 h0 = __float2bfloat16(v.x);
    __nv_bfloat16 h1 = __float2bfloat16(v.y);
    __nv_bfloat16 h2 = __float2bfloat16(v.z);
    __nv_bfloat16 h3 = __float2bfloat16(v.w);
    __nv_bfloat16 l0 = __float2bfloat16(v.x - __bfloat162float(h0));
    __nv_bfloat16 l1 = __float2bfloat16(v.y - __bfloat162float(h1));
    __nv_bfloat16 l2 = __float2bfloat16(v.z - __bfloat162float(h2));
    __nv_bfloat16 l3 = __float2bfloat16(v.w - __bfloat162float(h3));
    *(uint2*)hiP = make_uint2(packbf(h0, h1), packbf(h2, h3));
    *(uint2*)loP = make_uint2(packbf(l0, l1), packbf(l2, l3));
}

// ==========================================================================
// Tensor-core GEMM (HMMA): C = A @ W^T + bias, bf16x3 compensated, fp32 acc.
// A:[M,K], W:[N,K] fp32 row-major. BM=BN=128, BK=32, 256 thr (8 warps, 2x4).
// smem: 4 tiles (Ahi,Alo,Bhi,Blo), each 128 rows x 32 bf16, row stride 80B.
// ==========================================================================
#define TSTRIDE 80
#define TILESZ  (128 * TSTRIDE)    // 10240
#define S_AHI   0
#define S_ALO   TILESZ
#define S_BHI   (2 * TILESZ)
#define S_BLO   (3 * TILESZ)
#define GSMEM   (4 * TILESZ)       // 40960 (<48KB)
#define KCHUNK  32                 // KDIM/32

template <bool SPLIT>
__device__ __forceinline__ void gemm_tc_body(const float* __restrict__ A,
                                             const float* __restrict__ W,
                                             const float* __restrict__ bias,
                                             float* __restrict__ C)
{
    __shared__ __align__(128) char smem[GSMEM];
    const uint32_t sbase = smem_u32(smem);

    const int t   = threadIdx.x;
    const int l   = t & 31;
    const int wid = t >> 5;
    const int wm  = wid & 1;       // 0..1 -> 64-row group
    const int wn  = wid >> 1;      // 0..3 -> 32-col group
    const int rowBlk = blockIdx.y * 128;
    const int colBlk = blockIdx.x * 128;

    // ---- global-load mapping: warp = 4 rows x 8 lanes x float4 (coalesced)
    const int lrow = t >> 3;                 // 0..31
    const int col4 = (t & 7) * 4;            // 0..28
    const float* Ap = A + (size_t)(rowBlk + lrow) * KDIM + col4;
    const float* Wp = W + (size_t)(colBlk + lrow) * KDIM + col4;
    const uint32_t stoff = (uint32_t)lrow * TSTRIDE + (uint32_t)col4 * 2;

    float acc[4][4][4];
#pragma unroll
    for (int mi = 0; mi < 4; mi++)
#pragma unroll
        for (int ni = 0; ni < 4; ni++)
#pragma unroll
            for (int k = 0; k < 4; k++) acc[mi][ni][k] = 0.f;

    // ---- ldmatrix addressing
    const uint32_t lr  = (uint32_t)(l & 15);
    const uint32_t lcb = (uint32_t)(l >> 4) * 16;
    const uint32_t aBase = sbase + S_AHI + (wm * 64 + lr) * TSTRIDE + lcb;
    const uint32_t bBase = sbase + S_BHI + (wn * 32 + lr) * TSTRIDE + lcb;

    float4 pfA[4], pfB[4];
#pragma unroll
    for (int i = 0; i < 4; i++) {
        pfA[i] = *(const float4*)(Ap + (size_t)(i * 32) * KDIM);
        pfB[i] = *(const float4*)(Wp + (size_t)(i * 32) * KDIM);
    }

    for (int c = 0; c < KCHUNK; c++) {
        // commit prefetched chunk to smem (fp32 -> bf16 hi/lo)
#pragma unroll
        for (int i = 0; i < 4; i++) {
            const uint32_t o = stoff + (uint32_t)i * (32 * TSTRIDE);
            cvt_split8(pfA[i], smem + S_AHI + o, smem + S_ALO + o);
            cvt_split8(pfB[i], smem + S_BHI + o, smem + S_BLO + o);
        }
        __syncthreads();

        if (c + 1 < KCHUNK) {
            const int ko = (c + 1) * 32;
#pragma unroll
            for (int i = 0; i < 4; i++) {
                pfA[i] = *(const float4*)(Ap + (size_t)(i * 32) * KDIM + ko);
                pfB[i] = *(const float4*)(Wp + (size_t)(i * 32) * KDIM + ko);
            }
        }

#pragma unroll
        for (int ks = 0; ks < 2; ks++) {
            const uint32_t ko = (uint32_t)ks * 32;
            uint32_t ah[4][4], al[4][4];
#pragma unroll
            for (int mi = 0; mi < 4; mi++) {
                ldsm4(ah[mi], aBase + mi * (16 * TSTRIDE) + ko);
                ldsm4(al[mi], aBase + TILESZ + mi * (16 * TSTRIDE) + ko);
            }
            uint32_t bh[2][4], bl[2][4];
#pragma unroll
            for (int g = 0; g < 2; g++) {
                ldsm4(bh[g], bBase + g * (16 * TSTRIDE) + ko);
                ldsm4(bl[g], bBase + TILESZ + g * (16 * TSTRIDE) + ko);
            }
#pragma unroll
            for (int mi = 0; mi < 4; mi++) {
#pragma unroll
                for (int ni = 0; ni < 4; ni++) {
                    const int g = ni >> 1, s = ni & 1;
                    mma16816(acc[mi][ni], ah[mi], bh[g][s], bh[g][s + 2]);
                    mma16816(acc[mi][ni], ah[mi], bl[g][s], bl[g][s + 2]);
                    mma16816(acc[mi][ni], al[mi], bh[g][s], bh[g][s + 2]);
                }
            }
        }
        __syncthreads();
    }

    // ---- epilogue: bias + store (fragment: rows l>>2/+8, cols (l&3)*2,+1)
#pragma unroll
    for (int mi = 0; mi < 4; mi++) {
        const int rBase = rowBlk + wm * 64 + mi * 16 + (l >> 2);
#pragma unroll
        for (int ni = 0; ni < 4; ni++) {
            const int n = colBlk + wn * 32 + ni * 8 + (l & 3) * 2;
            const float2 bb = *(const float2*)(bias + n);
#pragma unroll
            for (int h2 = 0; h2 < 2; h2++) {
                const int m = rBase + h2 * 8;
                float2 v;
                v.x = acc[mi][ni][h2 * 2 + 0] + bb.x;
                v.y = acc[mi][ni][h2 * 2 + 1] + bb.y;
                if (SPLIT) {
                    const int b = m >> 11;
                    const int s = m & (SEQ - 1);
                    const int h = n >> 6;
                    const int d = n & (DK - 1);
                    *(float2*)&C[(((size_t)(b * NUM_HEADS + h) * SEQ + s) * DK) + d] = v;
                } else {
                    *(float2*)&C[(size_t)m * DMODEL + n] = v;
                }
            }
        }
    }
}

__global__ __launch_bounds__(256, 1)
void qkv_tc_kernel(const float* __restrict__ Qin,
                   const float* __restrict__ Kin,
                   const float* __restrict__ Vin,
                   const float* __restrict__ Wq, const float* __restrict__ bq,
                   const float* __restrict__ Wk, const float* __restrict__ bk,
                   const float* __restrict__ Wv, const float* __restrict__ bv)
{
    const int z = blockIdx.z;
    const float* A    = (z == 0) ? Qin : (z == 1) ? Kin : Vin;
    const float* W    = (z == 0) ? Wq  : (z == 1) ? Wk  : Wv;
    const float* bias = (z == 0) ? bq  : (z == 1) ? bk  : bv;
    float* out = g_QKV + (size_t)z * BATCH * NUM_HEADS * SEQ * DK;
    gemm_tc_body<true>(A, W, bias, out);
}

__global__ __launch_bounds__(256, 1)
void out_tc_kernel(const float* __restrict__ Wo,
                   const float* __restrict__ bo,
                   float* __restrict__ out)
{
    gemm_tc_body<false>(g_O, Wo, bo, out);
}

// ==========================================================================
// Flash attention, fp32 SIMT (unchanged, known-correct).
// ==========================================================================
#define FPAD 68
#define SM_Q  0
#define SM_KP (64 * FPAD)
#define SM_V  (2 * 64 * FPAD)
#define FLASH_SMEM (3 * 64 * FPAD * 4)

__global__ __launch_bounds__(256)
void flash_attn_kernel()
{
    extern __shared__ float sm[];
    float* Qs = sm + SM_Q;
    float* KP = sm + SM_KP;
    float* Vs = sm + SM_V;

    const int t  = threadIdx.x;
    const int tx = t & 15;
    const int ty = t >> 4;
    const int q0 = blockIdx.x * 64;
    const int h  = blockIdx.y;
    const int b  = blockIdx.z;

    const size_t headBase = ((size_t)b * NUM_HEADS + h) * SEQ * DK;
    const float* Qg = g_QKV + 0ull * BATCH * NUM_HEADS * SEQ * DK + headBase;
    const float* Kg = g_QKV + 1ull * BATCH * NUM_HEADS * SEQ * DK + headBase;
    const float* Vg = g_QKV + 2ull * BATCH * NUM_HEADS * SEQ * DK + headBase;

    const float SCALE = 0.125f;

    {
        const int ds = ty * 4;
        const int rb = tx;
#pragma unroll
        for (int p = 0; p < 4; p++) {
            const int r = rb + p * 16;
            float4 q = *(const float4*)&Qg[(size_t)(q0 + r) * DK + ds];
            Qs[(ds + 0) * FPAD + r] = q.x * SCALE;
            Qs[(ds + 1) * FPAD + r] = q.y * SCALE;
            Qs[(ds + 2) * FPAD + r] = q.z * SCALE;
            Qs[(ds + 3) * FPAD + r] = q.w * SCALE;
        }
    }

    float o[4][4];
    float m_i[4], l_i[4];
#pragma unroll
    for (int i = 0; i < 4; i++) {
        m_i[i] = -1e30f; l_i[i] = 0.f;
#pragma unroll
        for (int d = 0; d < 4; d++) o[i][d] = 0.f;
    }
    __syncthreads();

    for (int j0 = 0; j0 < SEQ; j0 += 64) {
        {
            const int ds = ty * 4;
            const int rb = tx;
#pragma unroll
            for (int p = 0; p < 4; p++) {
                const int r = rb + p * 16;
                float4 k = *(const float4*)&Kg[(size_t)(j0 + r) * DK + ds];
                KP[(ds + 0) * FPAD + r] = k.x;
                KP[(ds + 1) * FPAD + r] = k.y;
                KP[(ds + 2) * FPAD + r] = k.z;
                KP[(ds + 3) * FPAD + r] = k.w;
            }
            const int dv = tx * 4;
            const int jb = ty;
#pragma unroll
            for (int p = 0; p < 4; p++) {
                const int j = jb + p * 16;
                float4 v = *(const float4*)&Vg[(size_t)(j0 + j) * DK + dv];
                *(float4*)&Vs[j * FPAD + dv] = v;
            }
        }
        __syncthreads();

        float s[4][4];
#pragma unroll
        for (int i = 0; i < 4; i++)
#pragma unroll
            for (int j = 0; j < 4; j++) s[i][j] = 0.f;

#pragma unroll 16
        for (int d = 0; d < 64; d++) {
            float4 a  = *(const float4*)&Qs[d * FPAD + ty * 4];
            float4 bv = *(const float4*)&KP[d * FPAD + tx * 4];
            s[0][0] += a.x * bv.x; s[0][1] += a.x * bv.y; s[0][2] += a.x * bv.z; s[0][3] += a.x * bv.w;
            s[1][0] += a.y * bv.x; s[1][1] += a.y * bv.y; s[1][2] += a.y * bv.z; s[1][3] += a.y * bv.w;
            s[2][0] += a.z * bv.x; s[2][1] += a.z * bv.y; s[2][2] += a.z * bv.z; s[2][3] += a.z * bv.w;
            s[3][0] += a.w * bv.x; s[3][1] += a.w * bv.y; s[3][2] += a.w * bv.z; s[3][3] += a.w * bv.w;
        }

#pragma unroll
        for (int i = 0; i < 4; i++) {
            float mx = fmaxf(fmaxf(s[i][0], s[i][1]), fmaxf(s[i][2], s[i][3]));
#pragma unroll
            for (int off = 1; off < 16; off <<= 1)
                mx = fmaxf(mx, __shfl_xor_sync(0xffffffffu, mx, off));
            const float mn   = fmaxf(m_i[i], mx);
            const float corr = __expf(m_i[i] - mn);
            m_i[i] = mn;
            float rs = 0.f;
#pragma unroll
            for (int j = 0; j < 4; j++) {
                s[i][j] = __expf(s[i][j] - mn);
                rs += s[i][j];
            }
#pragma unroll
            for (int off = 1; off < 16; off <<= 1)
                rs += __shfl_xor_sync(0xffffffffu, rs, off);
            l_i[i] = l_i[i] * corr + rs;
#pragma unroll
            for (int d = 0; d < 4; d++) o[i][d] *= corr;
        }

        __syncthreads();

#pragma unroll
        for (int i = 0; i < 4; i++) {
            float4 pv = make_float4(s[i][0], s[i][1], s[i][2], s[i][3]);
            *(float4*)&KP[(ty * 4 + i) * FPAD + tx * 4] = pv;
        }
        __syncthreads();

#pragma unroll 16
        for (int j = 0; j < 64; j++) {
            float4 bv = *(const float4*)&Vs[j * FPAD + tx * 4];
            float a0 = KP[(ty * 4 + 0) * FPAD + j];
            float a1 = KP[(ty * 4 + 1) * FPAD + j];
            float a2 = KP[(ty * 4 + 2) * FPAD + j];
            float a3 = KP[(ty * 4 + 3) * FPAD + j];
            o[0][0] += a0 * bv.x; o[0][1] += a0 * bv.y; o[0][2] += a0 * bv.z; o[0][3] += a0 * bv.w;
            o[1][0] += a1 * bv.x; o[1][1] += a1 * bv.y; o[1][2] += a1 * bv.z; o[1][3] += a1 * bv.w;
            o[2][0] += a2 * bv.x; o[2][1] += a2 * bv.y; o[2][2] += a2 * bv.z; o[2][3] += a2 * bv.w;
            o[3][0] += a3 * bv.x; o[3][1] += a3 * bv.y; o[3][2] += a3 * bv.z; o[3][3] += a3 * bv.w;
        }
        __syncthreads();
    }

#pragma unroll
    for (int i = 0; i < 4; i++) {
        const int rowg = q0 + ty * 4 + i;
        const float inv = 1.f / l_i[i];
        float4 ov = make_float4(o[i][0] * inv, o[i][1] * inv,
                                o[i][2] * inv, o[i][3] * inv);
        *(float4*)&g_O[((size_t)b * SEQ + rowg) * DMODEL + h * DK + tx * 4] = ov;
    }
}

// ==========================================================================
// launch
// ==========================================================================
extern "C" void kernel_launch(void* const* d_in, const int* in_sizes, int n_in,
                              void* d_out, int out_size)
{
    (void)in_sizes; (void)n_in; (void)out_size;
    const float* Qin = (const float*)d_in[0];
    const float* Kin = (const float*)d_in[1];
    const float* Vin = (const float*)d_in[2];
    const float* Wq  = (const float*)d_in[3];
    const float* bq  = (const float*)d_in[4];
    const float* Wk  = (const float*)d_in[5];
    const float* bk  = (const float*)d_in[6];
    const float* Wv  = (const float*)d_in[7];
    const float* bv  = (const float*)d_in[8];
    const float* Wo  = (const float*)d_in[9];
    const float* bo  = (const float*)d_in[10];
    float* out = (float*)d_out;

    cudaFuncSetAttribute(flash_attn_kernel,
                         cudaFuncAttributeMaxDynamicSharedMemorySize, FLASH_SMEM);

    dim3 gProj(DMODEL / 128, MROWS / 128, 3);
    qkv_tc_kernel<<<gProj, 256>>>(Qin, Kin, Vin, Wq, bq, Wk, bk, Wv, bv);

    dim3 gAttn(SEQ / 64, NUM_HEADS, BATCH);
    flash_attn_kernel<<<gAttn, 256, FLASH_SMEM>>>();

    dim3 gOut(DMODEL / 128, MROWS / 128, 1);
    out_tc_kernel<<<gOut, 256>>>(Wo, bo, out);
}

// round 4
// speedup vs baseline: 2.0256x; 1.5680x over previous
#include <cuda_runtime.h>
#include <cuda_bf16.h>
#include <math.h>
#include <stdint.h>

#define NUM_HEADS 16
#define DMODEL    1024
#define DK        64
#define BATCH     2
#define SEQ       2048
#define MROWS     (BATCH * SEQ)      // 4096
#define KDIM      1024

// ---------------- scratch (device globals; no allocation allowed) ----------
__device__ __align__(128) float g_QKV[3ull * BATCH * NUM_HEADS * SEQ * DK];
__device__ __align__(128) float g_O[(size_t)MROWS * DMODEL];

// ==========================================================================
// warp-MMA helpers (arch-agnostic PTX: valid on plain sm_103 target)
// ==========================================================================
__device__ __forceinline__ uint32_t smem_u32(const void* p) {
    uint32_t a;
    asm("{ .reg .u64 t; cvta.to.shared.u64 t, %1; cvt.u32.u64 %0, t; }"
        : "=r"(a) : "l"(p));
    return a;
}

__device__ __forceinline__ void ldsm4(uint32_t* r, uint32_t addr) {
    asm volatile("ldmatrix.sync.aligned.m8n8.x4.shared.b16 {%0,%1,%2,%3}, [%4];"
                 : "=r"(r[0]), "=r"(r[1]), "=r"(r[2]), "=r"(r[3])
                 : "r"(addr));
}

__device__ __forceinline__ void mma16816(float* c, const uint32_t* a,
                                         uint32_t b0, uint32_t b1) {
    asm volatile(
        "mma.sync.aligned.m16n8k16.row.col.f32.bf16.bf16.f32 "
        "{%0,%1,%2,%3}, {%4,%5,%6,%7}, {%8,%9}, {%0,%1,%2,%3};"
        : "+f"(c[0]), "+f"(c[1]), "+f"(c[2]), "+f"(c[3])
        : "r"(a[0]), "r"(a[1]), "r"(a[2]), "r"(a[3]), "r"(b0), "r"(b1));
}

__device__ __forceinline__ uint32_t packbf(__nv_bfloat16 a, __nv_bfloat16 b) {
    return (uint32_t)__bfloat16_as_ushort(a) |
           ((uint32_t)__bfloat16_as_ushort(b) << 16);
}

// fp32x4 -> hi bf16x4 (8B) + lo bf16x4 (8B)
__device__ __forceinline__ void cvt_split8(float4 v, char* hiP, char* loP) {
    __nv_bfloat16 h0 = __float2bfloat16(v.x);
    __nv_bfloat16 h1 = __float2bfloat16(v.y);
    __nv_bfloat16 h2 = __float2bfloat16(v.z);
    __nv_bfloat16 h3 = __float2bfloat16(v.w);
    __nv_bfloat16 l0 = __float2bfloat16(v.x - __bfloat162float(h0));
    __nv_bfloat16 l1 = __float2bfloat16(v.y - __bfloat162float(h1));
    __nv_bfloat16 l2 = __float2bfloat16(v.z - __bfloat162float(h2));
    __nv_bfloat16 l3 = __float2bfloat16(v.w - __bfloat162float(h3));
    *(uint2*)hiP = make_uint2(packbf(h0, h1), packbf(h2, h3));
    *(uint2*)loP = make_uint2(packbf(l0, l1), packbf(l2, l3));
}

// ==========================================================================
// Tensor-core GEMM (HMMA): unchanged from R3 (known correct, 229 TF/s raw).
// ==========================================================================
#define TSTRIDE 80
#define TILESZ  (128 * TSTRIDE)
#define S_AHI   0
#define S_ALO   TILESZ
#define S_BHI   (2 * TILESZ)
#define S_BLO   (3 * TILESZ)
#define GSMEM   (4 * TILESZ)
#define KCHUNK  32

template <bool SPLIT>
__device__ __forceinline__ void gemm_tc_body(const float* __restrict__ A,
                                             const float* __restrict__ W,
                                             const float* __restrict__ bias,
                                             float* __restrict__ C)
{
    __shared__ __align__(128) char smem[GSMEM];
    const uint32_t sbase = smem_u32(smem);

    const int t   = threadIdx.x;
    const int l   = t & 31;
    const int wid = t >> 5;
    const int wm  = wid & 1;
    const int wn  = wid >> 1;
    const int rowBlk = blockIdx.y * 128;
    const int colBlk = blockIdx.x * 128;

    const int lrow = t >> 3;
    const int col4 = (t & 7) * 4;
    const float* Ap = A + (size_t)(rowBlk + lrow) * KDIM + col4;
    const float* Wp = W + (size_t)(colBlk + lrow) * KDIM + col4;
    const uint32_t stoff = (uint32_t)lrow * TSTRIDE + (uint32_t)col4 * 2;

    float acc[4][4][4];
#pragma unroll
    for (int mi = 0; mi < 4; mi++)
#pragma unroll
        for (int ni = 0; ni < 4; ni++)
#pragma unroll
            for (int k = 0; k < 4; k++) acc[mi][ni][k] = 0.f;

    const uint32_t lr  = (uint32_t)(l & 15);
    const uint32_t lcb = (uint32_t)(l >> 4) * 16;
    const uint32_t aBase = sbase + S_AHI + (wm * 64 + lr) * TSTRIDE + lcb;
    const uint32_t bBase = sbase + S_BHI + (wn * 32 + lr) * TSTRIDE + lcb;

    float4 pfA[4], pfB[4];
#pragma unroll
    for (int i = 0; i < 4; i++) {
        pfA[i] = *(const float4*)(Ap + (size_t)(i * 32) * KDIM);
        pfB[i] = *(const float4*)(Wp + (size_t)(i * 32) * KDIM);
    }

    for (int c = 0; c < KCHUNK; c++) {
#pragma unroll
        for (int i = 0; i < 4; i++) {
            const uint32_t o = stoff + (uint32_t)i * (32 * TSTRIDE);
            cvt_split8(pfA[i], smem + S_AHI + o, smem + S_ALO + o);
            cvt_split8(pfB[i], smem + S_BHI + o, smem + S_BLO + o);
        }
        __syncthreads();

        if (c + 1 < KCHUNK) {
            const int ko = (c + 1) * 32;
#pragma unroll
            for (int i = 0; i < 4; i++) {
                pfA[i] = *(const float4*)(Ap + (size_t)(i * 32) * KDIM + ko);
                pfB[i] = *(const float4*)(Wp + (size_t)(i * 32) * KDIM + ko);
            }
        }

#pragma unroll
        for (int ks = 0; ks < 2; ks++) {
            const uint32_t ko = (uint32_t)ks * 32;
            uint32_t ah[4][4], al[4][4];
#pragma unroll
            for (int mi = 0; mi < 4; mi++) {
                ldsm4(ah[mi], aBase + mi * (16 * TSTRIDE) + ko);
                ldsm4(al[mi], aBase + TILESZ + mi * (16 * TSTRIDE) + ko);
            }
            uint32_t bh[2][4], bl[2][4];
#pragma unroll
            for (int g = 0; g < 2; g++) {
                ldsm4(bh[g], bBase + g * (16 * TSTRIDE) + ko);
                ldsm4(bl[g], bBase + TILESZ + g * (16 * TSTRIDE) + ko);
            }
#pragma unroll
            for (int mi = 0; mi < 4; mi++) {
#pragma unroll
                for (int ni = 0; ni < 4; ni++) {
                    const int g = ni >> 1, s = ni & 1;
                    mma16816(acc[mi][ni], ah[mi], bh[g][s], bh[g][s + 2]);
                    mma16816(acc[mi][ni], ah[mi], bl[g][s], bl[g][s + 2]);
                    mma16816(acc[mi][ni], al[mi], bh[g][s], bh[g][s + 2]);
                }
            }
        }
        __syncthreads();
    }

#pragma unroll
    for (int mi = 0; mi < 4; mi++) {
        const int rBase = rowBlk + wm * 64 + mi * 16 + (l >> 2);
#pragma unroll
        for (int ni = 0; ni < 4; ni++) {
            const int n = colBlk + wn * 32 + ni * 8 + (l & 3) * 2;
            const float2 bb = *(const float2*)(bias + n);
#pragma unroll
            for (int h2 = 0; h2 < 2; h2++) {
                const int m = rBase + h2 * 8;
                float2 v;
                v.x = acc[mi][ni][h2 * 2 + 0] + bb.x;
                v.y = acc[mi][ni][h2 * 2 + 1] + bb.y;
                if (SPLIT) {
                    const int b = m >> 11;
                    const int s = m & (SEQ - 1);
                    const int h = n >> 6;
                    const int d = n & (DK - 1);
                    *(float2*)&C[(((size_t)(b * NUM_HEADS + h) * SEQ + s) * DK) + d] = v;
                } else {
                    *(float2*)&C[(size_t)m * DMODEL + n] = v;
                }
            }
        }
    }
}

__global__ __launch_bounds__(256, 1)
void qkv_tc_kernel(const float* __restrict__ Qin,
                   const float* __restrict__ Kin,
                   const float* __restrict__ Vin,
                   const float* __restrict__ Wq, const float* __restrict__ bq,
                   const float* __restrict__ Wk, const float* __restrict__ bk,
                   const float* __restrict__ Wv, const float* __restrict__ bv)
{
    const int z = blockIdx.z;
    const float* A    = (z == 0) ? Qin : (z == 1) ? Kin : Vin;
    const float* W    = (z == 0) ? Wq  : (z == 1) ? Wk  : Wv;
    const float* bias = (z == 0) ? bq  : (z == 1) ? bk  : bv;
    float* out = g_QKV + (size_t)z * BATCH * NUM_HEADS * SEQ * DK;
    gemm_tc_body<true>(A, W, bias, out);
}

__global__ __launch_bounds__(256, 1)
void out_tc_kernel(const float* __restrict__ Wo,
                   const float* __restrict__ bo,
                   float* __restrict__ out)
{
    gemm_tc_body<false>(g_O, Wo, bo, out);
}

// ==========================================================================
// Flash attention on tensor cores (bf16x3 compensated).
// CTA = 128 queries of one (b,h); 8 warps x 16 rows; K-tiles of 64 keys.
// smem (bf16, row stride 72 elems = 144B, conflict-free ldmatrix):
//   Khi/Klo:  [64 key][64 d]   (row-major = B col-major for Q@K^T)
//   Vthi/Vtlo:[64 d][64 key]   (transposed = B col-major for P@V)
// Q staged through smem once, lives in registers as hi/lo A-fragments.
// ==========================================================================
#define FSTR   144                 // bytes per smem row
#define FT     (64 * FSTR)         // 9216 bytes per tile
#define F_KHI  0
#define F_KLO  FT
#define F_VHI  (2 * FT)
#define F_VLO  (3 * FT)
#define FSMEM  (4 * FT)            // 36864 bytes (static)

__global__ __launch_bounds__(256, 1)
void flash_tc_kernel()
{
    __shared__ __align__(128) char smem[FSMEM];
    const uint32_t sbase = smem_u32(smem);

    const int t  = threadIdx.x;
    const int l  = t & 31;
    const int w  = t >> 5;
    const int q0 = blockIdx.x * 128;
    const int h  = blockIdx.y;
    const int b  = blockIdx.z;

    const size_t headBase = ((size_t)b * NUM_HEADS + h) * SEQ * DK;
    const float* Qg = g_QKV + headBase;
    const float* Kg = g_QKV + 1ull * BATCH * NUM_HEADS * SEQ * DK + headBase;
    const float* Vg = g_QKV + 2ull * BATCH * NUM_HEADS * SEQ * DK + headBase;

    const float SCALE = 0.125f;

    // ---- stage Q (scaled) into smem, then ldmatrix into register frags ----
    {
        const int row  = t >> 1;
        const int half = (t & 1) * 32;
#pragma unroll
        for (int i = 0; i < 8; i++) {
            float4 q = *(const float4*)&Qg[(size_t)(q0 + row) * DK + half + 4 * i];
            q.x *= SCALE; q.y *= SCALE; q.z *= SCALE; q.w *= SCALE;
            const uint32_t o = (uint32_t)row * FSTR + (uint32_t)(half + 4 * i) * 2;
            cvt_split8(q, smem + o, smem + 2 * FT + o);   // hi @0, lo @18432
        }
    }
    __syncthreads();

    uint32_t qh[4][4], ql[4][4];
    {
        const uint32_t aBase = sbase + (uint32_t)(w * 16 + (l & 15)) * FSTR
                             + (uint32_t)(l >> 4) * 16;
#pragma unroll
        for (int kt = 0; kt < 4; kt++) {
            ldsm4(qh[kt], aBase + kt * 32);
            ldsm4(ql[kt], aBase + 2 * FT + kt * 32);
        }
    }
    __syncthreads();   // Q consumed; smem free for K/V tiles

    float o_[8][4];
#pragma unroll
    for (int j = 0; j < 8; j++)
#pragma unroll
        for (int k = 0; k < 4; k++) o_[j][k] = 0.f;
    float m0 = -1e30f, m1 = -1e30f, l0 = 0.f, l1 = 0.f;

    // per-thread smem bases for ldmatrix (rows l&15, k-half l>>4)
    const uint32_t lbase = sbase + (uint32_t)(l & 15) * FSTR + (uint32_t)(l >> 4) * 16;

    for (int j0 = 0; j0 < SEQ; j0 += 64) {
        // ---- load K tile -> Khi/Klo [key][d]; V tile -> Vthi/Vtlo [d][key]
        {
            const int key  = t >> 2;
            const int doff = (t & 3) * 16;
#pragma unroll
            for (int i = 0; i < 4; i++) {
                float4 kv = *(const float4*)&Kg[(size_t)(j0 + key) * DK + doff + 4 * i];
                const uint32_t o = (uint32_t)key * FSTR + (uint32_t)(doff + 4 * i) * 2;
                cvt_split8(kv, smem + F_KHI + o, smem + F_KLO + o);
            }
#pragma unroll
            for (int i = 0; i < 4; i++) {
                float4 vv = *(const float4*)&Vg[(size_t)(j0 + key) * DK + doff + 4 * i];
                const float vf[4] = {vv.x, vv.y, vv.z, vv.w};
#pragma unroll
                for (int c2 = 0; c2 < 4; c2++) {
                    const int d = doff + 4 * i + c2;
                    __nv_bfloat16 hi = __float2bfloat16(vf[c2]);
                    __nv_bfloat16 lo = __float2bfloat16(vf[c2] - __bfloat162float(hi));
                    const uint32_t o = (uint32_t)d * FSTR + (uint32_t)key * 2;
                    *(__nv_bfloat16*)(smem + F_VHI + o) = hi;
                    *(__nv_bfloat16*)(smem + F_VLO + o) = lo;
                }
            }
        }
        __syncthreads();

        // ---- S = (Q*scale) @ K^T  (bf16x3) ----
        float s[8][4];
#pragma unroll
        for (int j = 0; j < 8; j++)
#pragma unroll
            for (int k = 0; k < 4; k++) s[j][k] = 0.f;

#pragma unroll
        for (int kt = 0; kt < 4; kt++) {
#pragma unroll
            for (int kg = 0; kg < 4; kg++) {
                uint32_t kh[4], kl[4];
                ldsm4(kh, lbase + F_KHI + kg * (16 * FSTR) + kt * 32);
                ldsm4(kl, lbase + F_KLO + kg * (16 * FSTR) + kt * 32);
#pragma unroll
                for (int ss = 0; ss < 2; ss++) {
                    float* sc = s[2 * kg + ss];
                    mma16816(sc, qh[kt], kh[ss], kh[ss + 2]);
                    mma16816(sc, qh[kt], kl[ss], kl[ss + 2]);
                    mma16816(sc, ql[kt], kh[ss], kh[ss + 2]);
                }
            }
        }

        // ---- online softmax (rows r0 = l>>2, r1 = r0+8 within warp) ----
        {
            float mx0 = s[0][0], mx1 = s[0][2];
#pragma unroll
            for (int j = 0; j < 8; j++) {
                mx0 = fmaxf(mx0, fmaxf(s[j][0], s[j][1]));
                mx1 = fmaxf(mx1, fmaxf(s[j][2], s[j][3]));
            }
            mx0 = fmaxf(mx0, __shfl_xor_sync(0xffffffffu, mx0, 1));
            mx0 = fmaxf(mx0, __shfl_xor_sync(0xffffffffu, mx0, 2));
            mx1 = fmaxf(mx1, __shfl_xor_sync(0xffffffffu, mx1, 1));
            mx1 = fmaxf(mx1, __shfl_xor_sync(0xffffffffu, mx1, 2));

            const float mn0 = fmaxf(m0, mx0);
            const float mn1 = fmaxf(m1, mx1);
            const float c0 = __expf(m0 - mn0);
            const float c1 = __expf(m1 - mn1);
            m0 = mn0; m1 = mn1;

            float rs0 = 0.f, rs1 = 0.f;
#pragma unroll
            for (int j = 0; j < 8; j++) {
                s[j][0] = __expf(s[j][0] - mn0);
                s[j][1] = __expf(s[j][1] - mn0);
                s[j][2] = __expf(s[j][2] - mn1);
                s[j][3] = __expf(s[j][3] - mn1);
                rs0 += s[j][0] + s[j][1];
                rs1 += s[j][2] + s[j][3];
            }
            rs0 += __shfl_xor_sync(0xffffffffu, rs0, 1);
            rs0 += __shfl_xor_sync(0xffffffffu, rs0, 2);
            rs1 += __shfl_xor_sync(0xffffffffu, rs1, 1);
            rs1 += __shfl_xor_sync(0xffffffffu, rs1, 2);
            l0 = l0 * c0 + rs0;
            l1 = l1 * c1 + rs1;

#pragma unroll
            for (int j = 0; j < 8; j++) {
                o_[j][0] *= c0; o_[j][1] *= c0;
                o_[j][2] *= c1; o_[j][3] *= c1;
            }
        }

        // ---- O += P @ V  (bf16x3; P frags built from S frags in regs) ----
#pragma unroll
        for (int kt = 0; kt < 4; kt++) {
            uint32_t phi[4], plo[4];
#pragma unroll
            for (int half = 0; half < 2; half++) {        // frag 2kt, 2kt+1
                const float* sp = s[2 * kt + half];
#pragma unroll
                for (int rr = 0; rr < 2; rr++) {          // rows r0, r1
                    const float x = sp[2 * rr + 0], y = sp[2 * rr + 1];
                    __nv_bfloat16 hx = __float2bfloat16(x);
                    __nv_bfloat16 hy = __float2bfloat16(y);
                    __nv_bfloat16 lx = __float2bfloat16(x - __bfloat162float(hx));
                    __nv_bfloat16 ly = __float2bfloat16(y - __bfloat162float(hy));
                    phi[2 * half + rr] = packbf(hx, hy);
                    plo[2 * half + rr] = packbf(lx, ly);
                }
            }
            // reorder: a-frag = {f0.r0, f0.r1, f1.r0, f1.r1} -> already built
            // as [half*2 + rr] = {f0r0, f0r1, f1r0, f1r1}  ✓
#pragma unroll
            for (int dg = 0; dg < 4; dg++) {
                uint32_t vh[4], vl[4];
                ldsm4(vh, lbase + F_VHI + dg * (16 * FSTR) + kt * 32);
                ldsm4(vl, lbase + F_VLO + dg * (16 * FSTR) + kt * 32);
#pragma unroll
                for (int ss = 0; ss < 2; ss++) {
                    float* oc = o_[2 * dg + ss];
                    mma16816(oc, phi, vh[ss], vh[ss + 2]);
                    mma16816(oc, phi, vl[ss], vl[ss + 2]);
                    mma16816(oc, plo, vh[ss], vh[ss + 2]);
                }
            }
        }
        __syncthreads();   // done reading this tile before next overwrite
    }

    // ---- epilogue: normalize, write merged-head [b*S, DMODEL] ----
    {
        const float inv0 = 1.f / l0;
        const float inv1 = 1.f / l1;
        const int r0 = q0 + w * 16 + (l >> 2);
        const int r1 = r0 + 8;
#pragma unroll
        for (int j = 0; j < 8; j++) {
            const int d = h * DK + j * 8 + (l & 3) * 2;
            *(float2*)&g_O[((size_t)b * SEQ + r0) * DMODEL + d] =
                make_float2(o_[j][0] * inv0, o_[j][1] * inv0);
            *(float2*)&g_O[((size_t)b * SEQ + r1) * DMODEL + d] =
                make_float2(o_[j][2] * inv1, o_[j][3] * inv1);
        }
    }
}

// ==========================================================================
// launch
// ==========================================================================
extern "C" void kernel_launch(void* const* d_in, const int* in_sizes, int n_in,
                              void* d_out, int out_size)
{
    (void)in_sizes; (void)n_in; (void)out_size;
    const float* Qin = (const float*)d_in[0];
    const float* Kin = (const float*)d_in[1];
    const float* Vin = (const float*)d_in[2];
    const float* Wq  = (const float*)d_in[3];
    const float* bq  = (const float*)d_in[4];
    const float* Wk  = (const float*)d_in[5];
    const float* bk  = (const float*)d_in[6];
    const float* Wv  = (const float*)d_in[7];
    const float* bv  = (const float*)d_in[8];
    const float* Wo  = (const float*)d_in[9];
    const float* bo  = (const float*)d_in[10];
    float* out = (float*)d_out;

    dim3 gProj(DMODEL / 128, MROWS / 128, 3);
    qkv_tc_kernel<<<gProj, 256>>>(Qin, Kin, Vin, Wq, bq, Wk, bk, Wv, bv);

    dim3 gAttn(SEQ / 128, NUM_HEADS, BATCH);
    flash_tc_kernel<<<gAttn, 256>>>();

    dim3 gOut(DMODEL / 128, MROWS / 128, 1);
    out_tc_kernel<<<gOut, 256>>>(Wo, bo, out);
}